// round 9
// baseline (speedup 1.0000x reference)
#include <cuda_runtime.h>
#include <cstdint>

// Foveated tokenizer: 5-level box-average pyramid over (3,4096,4096) int32 image.
// Token boxes exactly partition the image -> each pixel read exactly once.
// ~201 MB read + 3 MB write (float32 out), pure DRAM stream.
// R8: smem-free / barrier-free. Every CTA reads exactly 32KB; box reductions
//     happen in-thread (int4 accumulate) + shfl_xor butterfly. Grid 6144.

#define IMG_DIM 4096
#define IMG_CH_STRIDE (IMG_DIM * IMG_DIM)

// Job layout (uniform 32KB per CTA, heavy levels first):
//   level 4: 576 (tok,ch) * 8 chunks      = 4608 CTAs  [0, 4608)
//   level 3: 576 (tok,ch) * 2 chunks      = 1152 CTAs  [4608, 5760)
//   level 2: 576 jobs / 2 per CTA         =  288 CTAs  [5760, 6048)
//   level 1: 576 jobs / 8 per CTA         =   72 CTAs  [6048, 6120)
//   level 0: 768 jobs / 32 per CTA        =   24 CTAs  [6120, 6144)
#define N_JOBS 6144

template <int LEVEL>
__device__ __forceinline__ int2 tok_rowcol(int tl) {
    if (LEVEL == 0) return make_int2(tl >> 4, tl & 15);
    // ring = 4 at every level >= 1
    if (tl < 64)  return make_int2(tl >> 4, tl & 15);
    if (tl < 128) { int k = tl - 64; int r = k & 7;
                    return make_int2(4 + (k >> 3), (r < 4) ? r : (r + 8)); }
    int k = tl - 128; return make_int2(12 + (k >> 4), k & 15);
}

// ---- Level 4 (s=16): 8 lanes per box (4 vec-cols x 2 row-groups of 8 rows) ----
__device__ __forceinline__ void level4(int job, const int* __restrict__ img,
                                       float* __restrict__ out) {
    const int tl = job / 24, rem = job % 24, ch = rem >> 3, chunk = rem & 7;
    const int2 rc = tok_rowcol<4>(tl);
    const int cx = 256 * rc.y;                 // CORNER = 0
    const int cy = 256 * rc.x;
    const int oy0 = chunk * 2;                 // 2 output rows per CTA
    const int tid = threadIdx.x;
    const int oy  = tid >> 7;
    const int box = (tid >> 3) & 15;
    const int sub = tid & 7;
    const int vq  = sub & 3, rg = sub >> 2;
    const int row0 = cy + (oy0 + oy) * 16 + rg * 8;
    const int4* p = (const int4*)(img + (size_t)ch * IMG_CH_STRIDE
                                  + (size_t)row0 * IMG_DIM + cx) + box * 4 + vq;
    int4 a = make_int4(0, 0, 0, 0);
#pragma unroll
    for (int r = 0; r < 8; r++) {
        int4 t = __ldcs(p); p += IMG_DIM / 4;
        a.x += t.x; a.y += t.y; a.z += t.z; a.w += t.w;
    }
    int s = a.x + a.y + a.z + a.w;
    s += __shfl_xor_sync(0xffffffffu, s, 1);
    s += __shfl_xor_sync(0xffffffffu, s, 2);
    s += __shfl_xor_sync(0xffffffffu, s, 4);
    if (sub == 0) {
        const int n = 832 + tl;
        out[(((size_t)n * 3 + ch) << 8) + ((oy0 + oy) << 4) + box] = (float)(s >> 8);
    }
}

// ---- Level 3 (s=8): 2 lanes per box (2 vec-cols x full 8 rows) ----
__device__ __forceinline__ void level3(int job, const int* __restrict__ img,
                                       float* __restrict__ out) {
    const int tl = job / 6, rem = job % 6, ch = rem >> 1, chunk = rem & 1;
    const int2 rc = tok_rowcol<3>(tl);
    const int cx = 1024 + 128 * rc.y;
    const int cy = 1024 + 128 * rc.x;
    const int oy0 = chunk * 8;                 // 8 output rows per CTA
    const int tid = threadIdx.x;
    const int oy  = tid >> 5;
    const int box = (tid >> 1) & 15;
    const int sub = tid & 1;
    const int row0 = cy + (oy0 + oy) * 8;
    const int4* p = (const int4*)(img + (size_t)ch * IMG_CH_STRIDE
                                  + (size_t)row0 * IMG_DIM + cx) + box * 2 + sub;
    int4 a = make_int4(0, 0, 0, 0);
#pragma unroll
    for (int r = 0; r < 8; r++) {
        int4 t = __ldcs(p); p += IMG_DIM / 4;
        a.x += t.x; a.y += t.y; a.z += t.z; a.w += t.w;
    }
    int s = a.x + a.y + a.z + a.w;
    s += __shfl_xor_sync(0xffffffffu, s, 1);
    if (sub == 0) {
        const int n = 640 + tl;
        out[(((size_t)n * 3 + ch) << 8) + ((oy0 + oy) << 4) + box] = (float)(s >> 6);
    }
}

// ---- Level 2 (s=4): 1 thread per box (1 int4 x 4 rows); 2 jobs per CTA ----
__device__ __forceinline__ void level2(int pair, const int* __restrict__ img,
                                       float* __restrict__ out) {
    const int tid = threadIdx.x;
    const int oy = tid >> 4, bx = tid & 15;
#pragma unroll
    for (int jj = 0; jj < 2; jj++) {
        const int job = pair * 2 + jj;
        const int tl = job / 3, ch = job % 3;
        const int2 rc = tok_rowcol<2>(tl);
        const int cx = 1536 + 64 * rc.y;
        const int cy = 1536 + 64 * rc.x;
        const int row0 = cy + oy * 4;
        const int4* p = (const int4*)(img + (size_t)ch * IMG_CH_STRIDE
                                      + (size_t)row0 * IMG_DIM + cx) + bx;
        int4 a = make_int4(0, 0, 0, 0);
#pragma unroll
        for (int r = 0; r < 4; r++) {
            int4 t = __ldcs(p); p += IMG_DIM / 4;
            a.x += t.x; a.y += t.y; a.z += t.z; a.w += t.w;
        }
        const int n = 448 + tl;
        out[(((size_t)n * 3 + ch) << 8) + (oy << 4) + bx] =
            (float)((a.x + a.y + a.z + a.w) >> 4);
    }
}

// ---- Level 1 (s=2): thread owns 2 boxes (one int4 x 2 rows); 8 jobs per CTA ----
__device__ __forceinline__ void level1(int cta, const int* __restrict__ img,
                                       float* __restrict__ out) {
    const int tid = threadIdx.x;
#pragma unroll
    for (int k = 0; k < 4; k++) {
        const int slot = tid + 256 * k;        // 1024 slots = 8 jobs x 128
        const int j = slot >> 7, t = slot & 127;
        const int job = cta * 8 + j;
        const int tl = job / 3, ch = job % 3;
        const int2 rc = tok_rowcol<1>(tl);
        const int cx = 1792 + 32 * rc.y;
        const int cy = 1792 + 32 * rc.x;
        const int oy = t >> 3, pxq = t & 7;
        const int row0 = cy + oy * 2;
        const int4* p = (const int4*)(img + (size_t)ch * IMG_CH_STRIDE
                                      + (size_t)row0 * IMG_DIM + cx) + pxq;
        int4 t0 = __ldcs(p);
        int4 t1 = __ldcs(p + IMG_DIM / 4);
        const int b0 = t0.x + t0.y + t1.x + t1.y;
        const int b1 = t0.z + t0.w + t1.z + t1.w;
        const int n = 256 + tl;
        float2 v = make_float2((float)(b0 >> 2), (float)(b1 >> 2));
        *(float2*)&out[(((size_t)n * 3 + ch) << 8) + (oy << 4) + pxq * 2] = v;
    }
}

// ---- Level 0 (s=1): straight int4 -> float4 copy; 32 jobs per CTA ----
__device__ __forceinline__ void level0(int cta, const int* __restrict__ img,
                                       float* __restrict__ out) {
    const int tid = threadIdx.x;
#pragma unroll
    for (int k = 0; k < 8; k++) {
        const int slot = tid + 256 * k;        // 2048 slots = 32 jobs x 64
        const int j = slot >> 6, t = slot & 63;
        const int job = cta * 32 + j;
        const int tl = job / 3, ch = job % 3;
        const int2 rc = tok_rowcol<0>(tl);
        const int cx = 1920 + 16 * rc.y;
        const int cy = 1920 + 16 * rc.x;
        const int oy = t >> 2, vq = t & 3;
        int4 v = __ldcs((const int4*)(img + (size_t)ch * IMG_CH_STRIDE
                                      + (size_t)(cy + oy) * IMG_DIM + cx) + vq);
        float4 f = make_float4((float)v.x, (float)v.y, (float)v.z, (float)v.w);
        *(float4*)&out[(((size_t)tl * 3 + ch) << 8) + (oy << 4) + vq * 4] = f;
    }
}

__global__ void __launch_bounds__(256) foveator_kernel(const int* __restrict__ img,
                                                       float* __restrict__ out) {
    const int b = blockIdx.x;
    if (b < 4608)      level4(b,        img, out);
    else if (b < 5760) level3(b - 4608, img, out);
    else if (b < 6048) level2(b - 5760, img, out);
    else if (b < 6120) level1(b - 6048, img, out);
    else               level0(b - 6120, img, out);
}

extern "C" void kernel_launch(void* const* d_in, const int* in_sizes, int n_in,
                              void* d_out, int out_size) {
    const int* img = (const int*)d_in[0];
    float* out = (float*)d_out;
    foveator_kernel<<<N_JOBS, 256>>>(img, out);
}

// round 10
// speedup vs baseline: 1.0009x; 1.0009x over previous
#include <cuda_runtime.h>
#include <cstdint>

// Foveated tokenizer: 5-level box-average pyramid over (3,4096,4096) int32 image.
// Token boxes exactly partition the image -> each pixel read exactly once.
// ~201 MB read + 3 MB write (float32 out), pure DRAM stream.
// R9: levels 4/3 use the proven R7 smem two-phase (RPT=8, all threads load,
//     regs<=32 pinned via launch_bounds(256,8)); levels 2/1/0 use merged
//     direct handlers (2/8/32 jobs per CTA). Grid 6144.

#define IMG_DIM 4096
#define IMG_CH_STRIDE (IMG_DIM * IMG_DIM)

// Job layout (heavy levels first):
//   level 4: 576 (tok,ch) * 8 chunks = 4608 CTAs  [0, 4608)
//   level 3: 576 (tok,ch) * 2 chunks = 1152 CTAs  [4608, 5760)
//   level 2: 576 jobs / 2 per CTA    =  288 CTAs  [5760, 6048)
//   level 1: 576 jobs / 8 per CTA    =   72 CTAs  [6048, 6120)
//   level 0: 768 jobs / 32 per CTA   =   24 CTAs  [6120, 6144)
#define N_JOBS 6144

template <int LEVEL>
__device__ __forceinline__ int2 tok_rowcol(int tl) {
    if (LEVEL == 0) return make_int2(tl >> 4, tl & 15);
    // ring = 4 at every level >= 1
    if (tl < 64)  return make_int2(tl >> 4, tl & 15);
    if (tl < 128) { int k = tl - 64; int r = k & 7;
                    return make_int2(4 + (k >> 3), (r < 4) ? r : (r + 8)); }
    int k = tl - 128; return make_int2(12 + (k >> 4), k & 15);
}

// ---- Heavy levels (4, 3): R7 smem two-phase; all 256 threads issue 8 LDG.128 ----
template <int LEVEL>
__device__ __forceinline__ void process_heavy(int job,
                                              const int* __restrict__ img,
                                              float* __restrict__ out,
                                              int* psum) {
    constexpr int S    = 1 << LEVEL;
    constexpr int CHK  = (LEVEL == 4) ? 8 : 2;          // chunks per (tok,ch)
    constexpr int NR   = 16 / CHK;                      // output rows per chunk
    constexpr int W    = 16 * S;                        // region width (px)
    constexpr int VC   = W / 4;                         // int4 columns
    constexpr int RPT  = 8;                             // rows per thread
    constexpr int NGE  = S / RPT > 0 ? S / RPT : 1;     // row-groups per out-row
    constexpr int TOKBASE = (LEVEL == 4) ? 832 : 640;
    constexpr int PER_TOK = 3 * CHK;
    constexpr int CORNER  = 2048 - 128 * S;

    const int tl    = job / PER_TOK;
    const int rem   = job - tl * PER_TOK;
    const int ch    = rem / CHK;
    const int chunk = rem - ch * CHK;

    const int2 rc = tok_rowcol<LEVEL>(tl);
    const int cx  = CORNER + W * rc.y;                  // 16B aligned
    const int cy  = CORNER + W * rc.x;
    const int oy0 = chunk * NR;
    const int ry0 = cy + S * oy0;

    const int* base = img + (size_t)ch * IMG_CH_STRIDE;
    const int tid = threadIdx.x;

    // Phase 1: thread = (row-group g, vec-col); 8 front-batched LDG.128.
    {
        const int vcol = tid & (VC - 1);
        const int g    = tid / VC;
        const int4* p  = (const int4*)(base + (size_t)(ry0 + g * RPT) * IMG_DIM + cx)
                         + vcol;
        int4 a = make_int4(0, 0, 0, 0);
#pragma unroll
        for (int r = 0; r < RPT; r++) {
            int4 t = __ldcs(p);
            p += IMG_DIM / 4;
            a.x += t.x; a.y += t.y; a.z += t.z; a.w += t.w;
        }
        ((int4*)psum)[g * VC + vcol] = a;               // conflict-free 16B STS
    }
    __syncthreads();

    // Phase 2: combine NGE row-group partials x S columns per output box.
    constexpr int NOUT = NR * 16;
    const int n = TOKBASE + tl;
    for (int o = tid; o < NOUT; o += 256) {
        const int oy = o >> 4;
        const int bx = o & 15;
        int sum = 0;
#pragma unroll
        for (int gg = 0; gg < NGE; gg++) {
            const int* s = psum + (oy * NGE + gg) * W + (bx << LEVEL);
#pragma unroll
            for (int i = 0; i < S; i++) sum += s[i];
        }
        out[(((size_t)n * 3 + ch) << 8) + ((size_t)(oy0 + oy) << 4) + bx] =
            (float)(sum >> (2 * LEVEL));                // exact floor-div by S*S
    }
}

// ---- Level 2 (s=4): 1 thread per box (1 int4 x 4 rows); 2 jobs per CTA ----
__device__ __forceinline__ void level2(int pair, const int* __restrict__ img,
                                       float* __restrict__ out) {
    const int tid = threadIdx.x;
    const int oy = tid >> 4, bx = tid & 15;
#pragma unroll
    for (int jj = 0; jj < 2; jj++) {
        const int job = pair * 2 + jj;
        const int tl = job / 3, ch = job % 3;
        const int2 rc = tok_rowcol<2>(tl);
        const int cx = 1536 + 64 * rc.y;
        const int cy = 1536 + 64 * rc.x;
        const int4* p = (const int4*)(img + (size_t)ch * IMG_CH_STRIDE
                                      + (size_t)(cy + oy * 4) * IMG_DIM + cx) + bx;
        int4 a = make_int4(0, 0, 0, 0);
#pragma unroll
        for (int r = 0; r < 4; r++) {
            int4 t = __ldcs(p); p += IMG_DIM / 4;
            a.x += t.x; a.y += t.y; a.z += t.z; a.w += t.w;
        }
        const int n = 448 + tl;
        out[(((size_t)n * 3 + ch) << 8) + (oy << 4) + bx] =
            (float)((a.x + a.y + a.z + a.w) >> 4);
    }
}

// ---- Level 1 (s=2): thread owns 2 boxes (one int4 x 2 rows); 8 jobs per CTA ----
__device__ __forceinline__ void level1(int cta, const int* __restrict__ img,
                                       float* __restrict__ out) {
    const int tid = threadIdx.x;
#pragma unroll
    for (int k = 0; k < 4; k++) {
        const int slot = tid + 256 * k;                 // 1024 = 8 jobs x 128
        const int j = slot >> 7, t = slot & 127;
        const int job = cta * 8 + j;
        const int tl = job / 3, ch = job % 3;
        const int2 rc = tok_rowcol<1>(tl);
        const int cx = 1792 + 32 * rc.y;
        const int cy = 1792 + 32 * rc.x;
        const int oy = t >> 3, pxq = t & 7;
        const int4* p = (const int4*)(img + (size_t)ch * IMG_CH_STRIDE
                                      + (size_t)(cy + oy * 2) * IMG_DIM + cx) + pxq;
        int4 t0 = __ldcs(p);
        int4 t1 = __ldcs(p + IMG_DIM / 4);
        const int b0 = t0.x + t0.y + t1.x + t1.y;
        const int b1 = t0.z + t0.w + t1.z + t1.w;
        const int n = 256 + tl;
        float2 v = make_float2((float)(b0 >> 2), (float)(b1 >> 2));
        *(float2*)&out[(((size_t)n * 3 + ch) << 8) + (oy << 4) + pxq * 2] = v;
    }
}

// ---- Level 0 (s=1): straight int4 -> float4 copy; 32 jobs per CTA ----
__device__ __forceinline__ void level0(int cta, const int* __restrict__ img,
                                       float* __restrict__ out) {
    const int tid = threadIdx.x;
#pragma unroll
    for (int k = 0; k < 8; k++) {
        const int slot = tid + 256 * k;                 // 2048 = 32 jobs x 64
        const int j = slot >> 6, t = slot & 63;
        const int job = cta * 32 + j;
        const int tl = job / 3, ch = job % 3;
        const int2 rc = tok_rowcol<0>(tl);
        const int cx = 1920 + 16 * rc.y;
        const int cy = 1920 + 16 * rc.x;
        const int oy = t >> 2, vq = t & 3;
        int4 v = __ldcs((const int4*)(img + (size_t)ch * IMG_CH_STRIDE
                                      + (size_t)(cy + oy) * IMG_DIM + cx) + vq);
        float4 f = make_float4((float)v.x, (float)v.y, (float)v.z, (float)v.w);
        *(float4*)&out[(((size_t)tl * 3 + ch) << 8) + (oy << 4) + vq * 4] = f;
    }
}

__global__ void __launch_bounds__(256, 8)
foveator_kernel(const int* __restrict__ img, float* __restrict__ out) {
    __shared__ int psum[1024];                          // 4KB, heavy levels only
    const int b = blockIdx.x;
    if (b < 4608)      process_heavy<4>(b,        img, out, psum);
    else if (b < 5760) process_heavy<3>(b - 4608, img, out, psum);
    else if (b < 6048) level2(b - 5760, img, out);
    else if (b < 6120) level1(b - 6048, img, out);
    else               level0(b - 6120, img, out);
}

extern "C" void kernel_launch(void* const* d_in, const int* in_sizes, int n_in,
                              void* d_out, int out_size) {
    const int* img = (const int*)d_in[0];
    float* out = (float*)d_out;
    foveator_kernel<<<N_JOBS, 256>>>(img, out);
}

// round 11
// speedup vs baseline: 1.0017x; 1.0009x over previous
#include <cuda_runtime.h>
#include <cstdint>

// Foveated tokenizer: 5-level box-average pyramid over (3,4096,4096) int32 image.
// Token boxes exactly partition the image -> each pixel read exactly once.
// ~201 MB read + 3 MB write (float32 out), pure DRAM stream.
// R10: R7 job decomposition (proven 33.5us) + persistent CTAs with an atomic
//      work queue: no wave-quantization, no wave-transition bubbles, perfect
//      dynamic load balance, tiny-job tail drain.

#define IMG_DIM 4096
#define IMG_CH_STRIDE (IMG_DIM * IMG_DIM)

// Job layout (heavy levels first; identical to R7):
//   level 4 (s=16): 192 tok * 3 ch * 8 chunks = 4608 jobs   [0, 4608)
//   level 3 (s= 8): 192 tok * 3 ch * 2 chunks = 1152 jobs   [4608, 5760)
//   level 2 (s= 4): 192 tok * 3 ch * 1 chunk  =  576 jobs   [5760, 6336)
//   level 1 (s= 2): 192 tok * 3 ch * 1 chunk  =  576 jobs   [6336, 6912)
//   level 0 (s= 1): 256 tok * 3 ch * 1 chunk  =  768 jobs   [6912, 7680)
#define N_JOBS 7680
#define N_CTAS 1216   // ~152 SMs * 8 resident CTAs; persistent

__device__ int g_job_counter;

template <int LEVEL>
__device__ __forceinline__ void process_level(int job,
                                              const int* __restrict__ img,
                                              float* __restrict__ out,
                                              int* psum) {
    constexpr int S    = 1 << LEVEL;           // box stride in pixels
    constexpr int CHK  = (LEVEL == 4) ? 8 : (LEVEL == 3) ? 2 : 1; // chunks/(tok,ch)
    constexpr int NR   = 16 / CHK;             // output rows per chunk
    constexpr int W    = 16 * S;               // region width in pixels
    constexpr int VC   = W / 4;                // int4 columns
    constexpr int ROWS = NR * S;               // image rows per chunk
    constexpr int ITEMS = ROWS * VC;           // (row, vcol) load items
    constexpr int RPT  = (ITEMS >= 1024) ? ITEMS / 256 : 1;  // rows per thread
    constexpr int NACT = ITEMS / RPT;          // active threads in phase 1
    constexpr int NGE  = (S >= RPT) ? S / RPT : 1;  // row-groups per out-row
    constexpr int TOKBASE =
        (LEVEL == 0) ? 0 : (LEVEL == 1) ? 256 : (LEVEL == 2) ? 448
                                            : (LEVEL == 3) ? 640 : 832;
    constexpr int PER_TOK = 3 * CHK;
    constexpr int CORNER  = 2048 - 128 * S;    // pixel offset of level's grid (16-aligned)

    const int tl    = job / PER_TOK;           // token index within level
    const int rem   = job - tl * PER_TOK;
    const int ch    = rem / CHK;
    const int chunk = rem - ch * CHK;

    // Map level-local token index -> (row, col) on the 16x16 coarse grid.
    int row, col;
    if (LEVEL == 0) {
        row = tl >> 4; col = tl & 15;
    } else {
        // ring = 4 at every level >= 1
        if (tl < 64)       { row = tl >> 4;             col = tl & 15; }
        else if (tl < 128) { int k = tl - 64; row = 4 + (k >> 3);
                             int r = k & 7;             col = (r < 4) ? r : (r + 8); }
        else               { int k = tl - 128; row = 12 + (k >> 4); col = k & 15; }
    }

    const int cx  = CORNER + W * col;          // region top-left pixel (16B aligned)
    const int cy  = CORNER + W * row;
    const int oy0 = chunk * NR;                // first output row of this chunk
    const int ry0 = cy + S * oy0;              // first image row of this chunk

    const int* base = img + (size_t)ch * IMG_CH_STRIDE;
    const int tid = threadIdx.x;

    // Phase 1: every active thread owns one int4 column slice of RPT rows.
    // Fully unrolled -> RPT front-batched LDG.128.
    if (tid < NACT) {
        const int vcol = tid & (VC - 1);
        const int g    = tid / VC;             // row-group index
        const int4* p  = (const int4*)(base + (size_t)(ry0 + g * RPT) * IMG_DIM + cx)
                         + vcol;
        int4 a = make_int4(0, 0, 0, 0);
#pragma unroll
        for (int r = 0; r < RPT; r++) {
            int4 t = __ldcs(p);
            p += IMG_DIM / 4;
            a.x += t.x; a.y += t.y; a.z += t.z; a.w += t.w;
        }
        ((int4*)psum)[g * VC + vcol] = a;      // conflict-free 16B STS
    }
    __syncthreads();

    // Phase 2: combine NGE row-group partials x S scalar columns per output box.
    constexpr int NOUT = NR * 16;
    const int n = TOKBASE + tl;
    for (int o = tid; o < NOUT; o += 256) {
        const int oy = o >> 4;
        const int bx = o & 15;
        int sum = 0;
#pragma unroll
        for (int gg = 0; gg < NGE; gg++) {
            const int* s = psum + (oy * NGE + gg) * W + (bx << LEVEL);
#pragma unroll
            for (int i = 0; i < S; i++) sum += s[i];
        }
        // Exact floor-div by S*S (sum >= 0); value fits in [0,255].
        out[(((size_t)n * 3 + ch) << 8) + ((size_t)(oy0 + oy) << 4) + bx] =
            (float)(sum >> (2 * LEVEL));
    }
}

__global__ void reset_counter_kernel() {
    if (threadIdx.x == 0 && blockIdx.x == 0) g_job_counter = 0;
}

__global__ void __launch_bounds__(256)
foveator_kernel(const int* __restrict__ img, float* __restrict__ out) {
    __shared__ int psum[1024];                 // 4KB partials
    __shared__ int s_job;

    for (;;) {
        __syncthreads();                       // protect s_job / psum reuse
        if (threadIdx.x == 0) s_job = atomicAdd(&g_job_counter, 1);
        __syncthreads();
        const int b = s_job;
        if (b >= N_JOBS) break;                // uniform exit across CTA

        if (b < 4608)      process_level<4>(b,         img, out, psum);
        else if (b < 5760) process_level<3>(b - 4608,  img, out, psum);
        else if (b < 6336) process_level<2>(b - 5760,  img, out, psum);
        else if (b < 6912) process_level<1>(b - 6336,  img, out, psum);
        else               process_level<0>(b - 6912,  img, out, psum);
    }
}

extern "C" void kernel_launch(void* const* d_in, const int* in_sizes, int n_in,
                              void* d_out, int out_size) {
    const int* img = (const int*)d_in[0];
    float* out = (float*)d_out;
    reset_counter_kernel<<<1, 32>>>();
    foveator_kernel<<<N_CTAS, 256>>>(img, out);
}

// round 12
// speedup vs baseline: 1.0604x; 1.0586x over previous
#include <cuda_runtime.h>
#include <cstdint>

// Foveated tokenizer: 5-level box-average pyramid over (3,4096,4096) int32 image.
// Token boxes exactly partition the image -> each pixel read exactly once.
// ~201 MB read + 3 MB write (float32 out), pure DRAM stream.
// R11: R7 decomposition (proven best) with level-4 jobs fattened to 64KB
//      (CHK=4, RPT=16, thread = one full box-column of one output row).
//      Heavy CTAs halved, tail still drains on tiny L1/L0 jobs.
//      Regs pinned via launch_bounds(256,8).

#define IMG_DIM 4096
#define IMG_CH_STRIDE (IMG_DIM * IMG_DIM)

// Job layout (heavy levels first):
//   level 4 (s=16): 192 tok * 3 ch * 4 chunks = 2304 jobs   [0, 2304)
//   level 3 (s= 8): 192 tok * 3 ch * 2 chunks = 1152 jobs   [2304, 3456)
//   level 2 (s= 4): 192 tok * 3 ch * 1 chunk  =  576 jobs   [3456, 4032)
//   level 1 (s= 2): 192 tok * 3 ch * 1 chunk  =  576 jobs   [4032, 4608)
//   level 0 (s= 1): 256 tok * 3 ch * 1 chunk  =  768 jobs   [4608, 5376)
#define N_JOBS 5376

template <int LEVEL>
__device__ __forceinline__ void process_level(int job,
                                              const int* __restrict__ img,
                                              float* __restrict__ out,
                                              int* psum) {
    constexpr int S    = 1 << LEVEL;           // box stride in pixels
    constexpr int CHK  = (LEVEL == 4) ? 4 : (LEVEL == 3) ? 2 : 1; // chunks/(tok,ch)
    constexpr int NR   = 16 / CHK;             // output rows per chunk
    constexpr int W    = 16 * S;               // region width in pixels
    constexpr int VC   = W / 4;                // int4 columns
    constexpr int ROWS = NR * S;               // image rows per chunk
    constexpr int ITEMS = ROWS * VC;           // (row, vcol) load items
    constexpr int RPT  = (ITEMS >= 1024) ? ITEMS / 256 : 1;  // rows per thread
    constexpr int NACT = ITEMS / RPT;          // active threads in phase 1
    constexpr int NGE  = (S >= RPT) ? S / RPT : 1;  // row-groups per out-row
    constexpr int TOKBASE =
        (LEVEL == 0) ? 0 : (LEVEL == 1) ? 256 : (LEVEL == 2) ? 448
                                            : (LEVEL == 3) ? 640 : 832;
    constexpr int PER_TOK = 3 * CHK;
    constexpr int CORNER  = 2048 - 128 * S;    // pixel offset of level's grid (16-aligned)

    const int tl    = job / PER_TOK;           // token index within level
    const int rem   = job - tl * PER_TOK;
    const int ch    = rem / CHK;
    const int chunk = rem - ch * CHK;

    // Map level-local token index -> (row, col) on the 16x16 coarse grid.
    int row, col;
    if (LEVEL == 0) {
        row = tl >> 4; col = tl & 15;
    } else {
        // ring = 4 at every level >= 1
        if (tl < 64)       { row = tl >> 4;             col = tl & 15; }
        else if (tl < 128) { int k = tl - 64; row = 4 + (k >> 3);
                             int r = k & 7;             col = (r < 4) ? r : (r + 8); }
        else               { int k = tl - 128; row = 12 + (k >> 4); col = k & 15; }
    }

    const int cx  = CORNER + W * col;          // region top-left pixel (16B aligned)
    const int cy  = CORNER + W * row;
    const int oy0 = chunk * NR;                // first output row of this chunk
    const int ry0 = cy + S * oy0;              // first image row of this chunk

    const int* base = img + (size_t)ch * IMG_CH_STRIDE;
    const int tid = threadIdx.x;

    // Phase 1: every active thread owns one int4 column slice of RPT rows.
    // Fully unrolled; ptxas batches LDG.128s under the 32-reg pin.
    if (tid < NACT) {
        const int vcol = tid & (VC - 1);
        const int g    = tid / VC;             // row-group index
        const int4* p  = (const int4*)(base + (size_t)(ry0 + g * RPT) * IMG_DIM + cx)
                         + vcol;
        int4 a = make_int4(0, 0, 0, 0);
#pragma unroll
        for (int r = 0; r < RPT; r++) {
            int4 t = __ldcs(p);
            p += IMG_DIM / 4;
            a.x += t.x; a.y += t.y; a.z += t.z; a.w += t.w;
        }
        ((int4*)psum)[g * VC + vcol] = a;      // conflict-free 16B STS
    }
    __syncthreads();

    // Phase 2: combine NGE row-group partials x S scalar columns per output box.
    constexpr int NOUT = NR * 16;
    const int n = TOKBASE + tl;
    for (int o = tid; o < NOUT; o += 256) {
        const int oy = o >> 4;
        const int bx = o & 15;
        int sum = 0;
#pragma unroll
        for (int gg = 0; gg < NGE; gg++) {
            const int* s = psum + (oy * NGE + gg) * W + (bx << LEVEL);
#pragma unroll
            for (int i = 0; i < S; i++) sum += s[i];
        }
        // Exact floor-div by S*S (sum >= 0); value fits in [0,255].
        out[(((size_t)n * 3 + ch) << 8) + ((size_t)(oy0 + oy) << 4) + bx] =
            (float)(sum >> (2 * LEVEL));
    }
}

__global__ void __launch_bounds__(256, 8)
foveator_kernel(const int* __restrict__ img, float* __restrict__ out) {
    __shared__ int psum[1024];                 // 4KB partials
    const int b = blockIdx.x;
    if (b < 2304)      process_level<4>(b,         img, out, psum);
    else if (b < 3456) process_level<3>(b - 2304,  img, out, psum);
    else if (b < 4032) process_level<2>(b - 3456,  img, out, psum);
    else if (b < 4608) process_level<1>(b - 4032,  img, out, psum);
    else               process_level<0>(b - 4608,  img, out, psum);
}

extern "C" void kernel_launch(void* const* d_in, const int* in_sizes, int n_in,
                              void* d_out, int out_size) {
    const int* img = (const int*)d_in[0];
    float* out = (float*)d_out;
    foveator_kernel<<<N_JOBS, 256>>>(img, out);
}